// round 1
// baseline (speedup 1.0000x reference)
#include <cuda_runtime.h>
#include <cuda_bf16.h>

// NeighborIntegration: B=64, K=64, D=128
//
// Reference math collapses (softmax over size-1 axis == 1; scalar row-mask
// commutes with the linear layer) to:
//   R[b,i,:]   = sum_j mask_n(b,i,j) * neighbor[b,i,j,:]
//   cnt_n[b,i] = sum_j mask_n(b,i,j)
//   v[b,i,:]   = 64*mask_c(b,i)*concept[b,i,:] + R[b,i,:]
//   scale      = 64*mask_c(b,i) + cnt_n[b,i]
//   y[b,i,:]   = 0.5 * ( v @ W1[0:128,:] + scale*( stu[b] @ W1[128:256,:] + b1 ) )
//
// One block per (b,i): streams 64 rows x 128 f32 (32 KiB) of neighbor_emb,
// then a tiny fused dual-GEMV with W1 (L1-resident after first block per SM).

#define D_ 128
#define K_ 64

__global__ __launch_bounds__(256)
void neighbor_integration_kernel(const float* __restrict__ stu,       // [64,128]
                                 const float* __restrict__ concept_,  // [64,64,128]
                                 const float* __restrict__ neigh,     // [64,64,64,128]
                                 const float* __restrict__ W1,        // [256,128] row-major
                                 const float* __restrict__ b1,        // [128]
                                 float* __restrict__ out)             // [64,64,128]
{
    const int bi   = blockIdx.x;        // b*64 + i
    const int b    = bi >> 6;
    const int tid  = threadIdx.x;
    const int w    = tid >> 5;          // warp 0..7
    const int lane = tid & 31;

    __shared__ float s_acc[8][D_];      // per-warp masked row accumulators
    __shared__ float s_cnt[8];          // per-warp masked-row counts
    __shared__ float s_red[8];          // concept-sum partial reduction
    __shared__ float s_v[D_];           // combined GEMV input vector
    __shared__ float s_stu[D_];         // stu row
    __shared__ float s_a2[D_];          // stu @ W1b + b1

    // ---------------- Phase 1: masked reduction over j -------------------
    // Warp w handles rows j = 8w .. 8w+7. Each lane loads float4 (4 floats),
    // so one row = 32 lanes * 16B = 512B fully coalesced.
    const float4* nrow = reinterpret_cast<const float4*>(neigh) +
                         (size_t)bi * (K_ * (D_ / 4));

    float4 r[8];
#pragma unroll
    for (int u = 0; u < 8; ++u) {
        const int j = w * 8 + u;
        r[u] = nrow[j * 32 + lane];     // 8 independent loads -> MLP=8/warp
    }

    float4 acc = make_float4(0.f, 0.f, 0.f, 0.f);
    float  cnt = 0.f;
#pragma unroll
    for (int u = 0; u < 8; ++u) {
        float s = r[u].x + r[u].y + r[u].z + r[u].w;
#pragma unroll
        for (int o = 16; o > 0; o >>= 1)
            s += __shfl_xor_sync(0xffffffffu, s, o);
        if (s != 0.0f) {                // mask_n (reference: row-sum != 0)
            acc.x += r[u].x; acc.y += r[u].y;
            acc.z += r[u].z; acc.w += r[u].w;
            cnt += 1.0f;
        }
    }
    reinterpret_cast<float4*>(s_acc[w])[lane] = acc;
    if (lane == 0) s_cnt[w] = cnt;
    __syncthreads();

    // ---------------- Phase 2: combine, masks, scalars --------------------
    float R = 0.f, c = 0.f, st = 0.f;
    if (tid < D_) {
#pragma unroll
        for (int ww = 0; ww < 8; ++ww) R += s_acc[ww][tid];
        c  = concept_[(size_t)bi * D_ + tid];
        st = stu[(size_t)b * D_ + tid];
    }
    // concept row sum (warps 0..3 carry data; 4..7 contribute zeros)
    float cs = c;
#pragma unroll
    for (int o = 16; o > 0; o >>= 1)
        cs += __shfl_xor_sync(0xffffffffu, cs, o);
    if (lane == 0) s_red[w] = cs;
    __syncthreads();

    const float csum  = s_red[0] + s_red[1] + s_red[2] + s_red[3];
    const float cntn  = s_cnt[0] + s_cnt[1] + s_cnt[2] + s_cnt[3] +
                        s_cnt[4] + s_cnt[5] + s_cnt[6] + s_cnt[7];
    const float maskc = (csum != 0.0f) ? 1.0f : 0.0f;
    const float scale = 64.0f * maskc + cntn;

    if (tid < D_) {
        s_v[tid]   = 64.0f * maskc * c + R;
        s_stu[tid] = st;
    }
    __syncthreads();

    // ---------------- Phase 3: fused dual GEMV ---------------------------
    // threads 0..127  : a1[d] = sum_k v[k]   * W1[k]    [d]
    // threads 128..255: a2[d] = sum_k stu[k] * W1[128+k][d] + b1[d]
    float a1 = 0.f;
    if (tid < D_) {
#pragma unroll 4
        for (int k = 0; k < D_; ++k)
            a1 = fmaf(s_v[k], W1[k * D_ + tid], a1);
    } else {
        const int d = tid - D_;
        float a2 = 0.f;
#pragma unroll 4
        for (int k = 0; k < D_; ++k)
            a2 = fmaf(s_stu[k], W1[(D_ + k) * D_ + d], a2);
        s_a2[d] = a2 + b1[d];
    }
    __syncthreads();

    if (tid < D_)
        out[(size_t)bi * D_ + tid] = 0.5f * (a1 + scale * s_a2[tid]);
}

extern "C" void kernel_launch(void* const* d_in, const int* in_sizes, int n_in,
                              void* d_out, int out_size)
{
    const float* stu      = (const float*)d_in[0];  // [64,128]
    const float* concept_ = (const float*)d_in[1];  // [64,64,128]
    const float* neigh    = (const float*)d_in[2];  // [64,64,64,128]
    const float* W1       = (const float*)d_in[3];  // [256,128]
    const float* b1       = (const float*)d_in[4];  // [128]
    // d_in[5] = Wn, d_in[6] = bn: dead code (softmax over size-1 axis == 1)
    float* out = (float*)d_out;

    neighbor_integration_kernel<<<64 * 64, 256>>>(stu, concept_, neigh, W1, b1, out);
}

// round 3
// speedup vs baseline: 1.4215x; 1.4215x over previous
#include <cuda_runtime.h>
#include <cuda_bf16.h>

// NeighborIntegration: B=64, K=64, D=128
//
// y[b,i] = 0.5*( (64*mask_c*concept[b,i] + sum_j mask_n*neigh[b,i,j]) @ W1a
//              + (64*mask_c + cnt_n) * (stu[b] @ W1b + b1) )
//
// Block = (b, 8 consecutive i).  Phase 0: cooperative a2 = stu@W1b + b1 (b-only,
// amortized over 8 rows).  Then each warp independently owns one i:
// streams its 64 neighbor rows (masked reduction via butterfly shuffles),
// and does the v@W1a GEMV entirely in registers (v broadcast via shuffles).

#define D_ 128
#define K_ 64

__device__ __forceinline__ float warp_sum(float x) {
#pragma unroll
    for (int o = 16; o > 0; o >>= 1)
        x += __shfl_xor_sync(0xffffffffu, x, o);
    return x;
}

__global__ __launch_bounds__(256)
void neighbor_integration_kernel(const float* __restrict__ stu,       // [64,128]
                                 const float* __restrict__ concept_,  // [64,64,128]
                                 const float* __restrict__ neigh,     // [64,64,64,128]
                                 const float* __restrict__ W1,        // [256,128]
                                 const float* __restrict__ b1,        // [128]
                                 float* __restrict__ out)             // [64,64,128]
{
    const int blk  = blockIdx.x;            // 512 blocks
    const int b    = blk >> 3;
    const int i0   = (blk & 7) << 3;
    const int tid  = threadIdx.x;
    const int w    = tid >> 5;              // warp 0..7  -> i = i0 + w
    const int lane = tid & 31;

    __shared__ float4 s_stu4[32];           // stu row [128]
    __shared__ float  s_p[256];             // a2 partials
    __shared__ float4 s_a24[32];            // a2 = stu@W1b + b1

    // ---- Phase 0: load stu row, compute a2 cooperatively (b-only) ----
    if (tid < 32)
        s_stu4[tid] = reinterpret_cast<const float4*>(stu + (size_t)b * D_)[tid];
    __syncthreads();

    {
        const float* s_stu = reinterpret_cast<const float*>(s_stu4);
        const int d    = tid & 127;
        const int half = tid >> 7;          // split k-range over 2 halves
        const int kb   = half * 64;
        float p = 0.f;
#pragma unroll 8
        for (int kk = 0; kk < 64; ++kk) {
            const int k = kb + kk;
            p = fmaf(s_stu[k], W1[(size_t)(D_ + k) * D_ + d], p);
        }
        s_p[tid] = p;
    }
    __syncthreads();
    if (tid < D_)
        reinterpret_cast<float*>(s_a24)[tid] = s_p[tid] + s_p[tid + 128] + b1[tid];
    __syncthreads();

    // ---- Per-warp: i = i0 + w, fully independent from here on ----
    const size_t bi = (size_t)b * 64 + (i0 + w);

    // Phase 1: masked streaming reduction over the 64 neighbor rows.
    const float4* nbase = reinterpret_cast<const float4*>(neigh) + bi * (K_ * 32);
    float4 acc = make_float4(0.f, 0.f, 0.f, 0.f);
    float  cnt = 0.f;

    for (int jb = 0; jb < K_; jb += 8) {
        float4 r[8];
#pragma unroll
        for (int u = 0; u < 8; ++u)
            r[u] = __ldcs(&nbase[(jb + u) * 32 + lane]);   // streaming hint
#pragma unroll
        for (int u = 0; u < 8; ++u) {
            const float rs = warp_sum((r[u].x + r[u].y) + (r[u].z + r[u].w));
            if (rs != 0.0f) {                              // mask_n (warp-uniform)
                acc.x += r[u].x; acc.y += r[u].y;
                acc.z += r[u].z; acc.w += r[u].w;
                cnt   += 1.0f;
            }
        }
    }

    // concept row + its mask
    const float4 cc = reinterpret_cast<const float4*>(concept_)[bi * 32 + lane];
    const float csum = warp_sum((cc.x + cc.y) + (cc.z + cc.w));
    const float mc   = (csum != 0.0f) ? 64.0f : 0.0f;      // 64 * mask_c
    const float scale = mc + cnt;

    float4 v;                                   // v[k], k = 4*lane .. 4*lane+3
    v.x = fmaf(mc, cc.x, acc.x);
    v.y = fmaf(mc, cc.y, acc.y);
    v.z = fmaf(mc, cc.z, acc.z);
    v.w = fmaf(mc, cc.w, acc.w);

    // Phase 3: o[d] = sum_k v[k] * W1a[k][d], d = 4*lane .. 4*lane+3.
    // v broadcast out of registers via shuffles; W1 rows via LDG.128 (L1-hot).
    float4 o = make_float4(0.f, 0.f, 0.f, 0.f);
#pragma unroll 4
    for (int k0 = 0; k0 < D_; k0 += 4) {
        const int src = k0 >> 2;
        const float vx = __shfl_sync(0xffffffffu, v.x, src);
        const float vy = __shfl_sync(0xffffffffu, v.y, src);
        const float vz = __shfl_sync(0xffffffffu, v.z, src);
        const float vw = __shfl_sync(0xffffffffu, v.w, src);
        const float4* wr = reinterpret_cast<const float4*>(W1 + (size_t)k0 * D_);
        const float4 w0 = wr[lane];
        const float4 w1r = wr[32 + lane];
        const float4 w2 = wr[64 + lane];
        const float4 w3 = wr[96 + lane];
        o.x = fmaf(vx, w0.x, o.x); o.y = fmaf(vx, w0.y, o.y);
        o.z = fmaf(vx, w0.z, o.z); o.w = fmaf(vx, w0.w, o.w);
        o.x = fmaf(vy, w1r.x, o.x); o.y = fmaf(vy, w1r.y, o.y);
        o.z = fmaf(vy, w1r.z, o.z); o.w = fmaf(vy, w1r.w, o.w);
        o.x = fmaf(vz, w2.x, o.x); o.y = fmaf(vz, w2.y, o.y);
        o.z = fmaf(vz, w2.z, o.z); o.w = fmaf(vz, w2.w, o.w);
        o.x = fmaf(vw, w3.x, o.x); o.y = fmaf(vw, w3.y, o.y);
        o.z = fmaf(vw, w3.z, o.z); o.w = fmaf(vw, w3.w, o.w);
    }

    const float4 a2 = s_a24[lane];
    float4 res;
    res.x = 0.5f * fmaf(scale, a2.x, o.x);
    res.y = 0.5f * fmaf(scale, a2.y, o.y);
    res.z = 0.5f * fmaf(scale, a2.z, o.z);
    res.w = 0.5f * fmaf(scale, a2.w, o.w);
    reinterpret_cast<float4*>(out)[bi * 32 + lane] = res;
}

extern "C" void kernel_launch(void* const* d_in, const int* in_sizes, int n_in,
                              void* d_out, int out_size)
{
    const float* stu      = (const float*)d_in[0];  // [64,128]
    const float* concept_ = (const float*)d_in[1];  // [64,64,128]
    const float* neigh    = (const float*)d_in[2];  // [64,64,64,128]
    const float* W1       = (const float*)d_in[3];  // [256,128]
    const float* b1       = (const float*)d_in[4];  // [128]
    // d_in[5]=Wn, d_in[6]=bn: dead (softmax over size-1 axis == 1)
    float* out = (float*)d_out;

    neighbor_integration_kernel<<<512, 256>>>(stu, concept_, neigh, W1, b1, out);
}